// round 10
// baseline (speedup 1.0000x reference)
#include <cuda_runtime.h>
#include <cuda_fp16.h>
#include <cstdint>

#define Bq 32
#define Sq 48
#define Lq 64
#define Fq 256

// ---------------- staged W1 in mma.sync B-fragment layout (fp16, single comp) ----------------
// g_Wf[(s*16 + nbp)*32 + lane] : uint4 = two n8-fragments {b0,b1} for nblocks 2*nbp, 2*nbp+1
__device__ __align__(16) uint4 g_Wf[16 * 16 * 32];   // 128KB

__device__ __forceinline__ uint32_t pack_h(float lo, float hi) {
    __half2 h = __floats2half2_rn(lo, hi);
    return *reinterpret_cast<uint32_t*>(&h);
}

__global__ void stage_w1_kernel(const float* __restrict__ W1) {
    int idx = blockIdx.x * 256 + threadIdx.x;   // 8192 uint4s
    int lane = idx & 31;
    int nbp  = (idx >> 5) & 15;
    int s    = idx >> 9;
    int g = lane >> 2, q = lane & 3;
    int k0 = s * 16 + q * 2;
    uint4 r;
    uint32_t* rr = reinterpret_cast<uint32_t*>(&r);
    #pragma unroll
    for (int h = 0; h < 2; ++h) {
        int col = (nbp * 2 + h) * 8 + g;
        rr[h * 2 + 0] = pack_h(W1[(k0 + 0) * 256 + col], W1[(k0 + 1) * 256 + col]);
        rr[h * 2 + 1] = pack_h(W1[(k0 + 8) * 256 + col], W1[(k0 + 9) * 256 + col]);
    }
    g_Wf[idx] = r;
}

// ---------------- helpers ----------------
__device__ __forceinline__ uint32_t smem_u32(const void* p) {
    uint32_t a;
    asm("{ .reg .u64 t; cvta.to.shared.u64 t, %1; cvt.u32.u64 %0, t; }" : "=r"(a) : "l"(p));
    return a;
}
__device__ __forceinline__ void cp16(uint32_t dst, const void* src) {
    asm volatile("cp.async.ca.shared.global [%0], [%1], 16;" :: "r"(dst), "l"(src));
}
#define CP_COMMIT() asm volatile("cp.async.commit_group;" ::: "memory")
#define CP_WAIT0()  asm volatile("cp.async.wait_group 0;" ::: "memory")

__device__ __forceinline__ void mma16816(float* c, const uint4& a, uint32_t b0, uint32_t b1) {
    asm volatile(
        "mma.sync.aligned.m16n8k16.row.col.f32.f16.f16.f32 "
        "{%0,%1,%2,%3},{%4,%5,%6,%7},{%8,%9},{%0,%1,%2,%3};"
        : "+f"(c[0]), "+f"(c[1]), "+f"(c[2]), "+f"(c[3])
        : "r"(a.x), "r"(a.y), "r"(a.z), "r"(a.w), "r"(b0), "r"(b1));
}

// ---------------- SMEM layout (bytes) ----------------
// Xf: A-fragment layout [s 16][comp 2][mtg 4][lane 32] uint4 = 64KB  (comp: Ah, Al)
static constexpr int XF_OFF   = 0;
static constexpr int WB_OFF   = 65536;    // 2 stages x 8KB
static constexpr int PRED_OFF = 81920;    // float4[256] = 4KB (epilogue pred aliases first 1KB)
static constexpr int W2B1_OFF = 86016;    // float2[256] = 2KB
static constexpr int INVD_OFF = 88064;    // float[64]
static constexpr int SC_OFF   = 88320;    // float[64]
static constexpr int WGT_OFF  = 88576;    // float[64]
static constexpr int SMEM_BYTES = 88832;

__global__ __launch_bounds__(256, 2)
void ida_mma_kernel(const float* __restrict__ features,
                    const float* __restrict__ src_locs,
                    const float* __restrict__ tar_locs,
                    const float* __restrict__ b1,
                    const float* __restrict__ W2,
                    const float* __restrict__ b2,
                    float* __restrict__ out)
{
    extern __shared__ char smem[];
    const uint32_t sb = smem_u32(smem);
    const int t      = threadIdx.x;
    const int lane   = t & 31;
    const int wid    = t >> 5;
    const int warp_m = wid & 1;        // rows [warp_m*32, +32)
    const int warp_n = wid >> 1;       // cols [warp_n*64, +64)
    const int g      = lane >> 2;
    const int q      = lane & 3;
    const int bs     = blockIdx.x;
    const int b      = bs / Sq;

    // ---- prologue: cp.async W step 0 into stage 0 ----
    {
        #pragma unroll
        for (int j = 0; j < 2; ++j) {
            int seg = t + j * 256;               // 512 uint4s
            cp16(sb + WB_OFF + seg * 16, g_Wf + seg);
        }
        CP_COMMIT();
    }

    // ---- convert X (64x256 f32) into fp16 A-fragment layout, hi + lo ----
    {
        const float4* gx = reinterpret_cast<const float4*>(features + (size_t)bs * (Lq * Fq));
        #pragma unroll
        for (int r = 0; r < 16; ++r) {
            int idx = t + r * 256;          // float4 index = m*64 + qq
            int m = idx >> 6, qq = idx & 63;
            float4 x = gx[idx];
            int s     = qq >> 2;
            int colk4 = qq & 3;
            int mtg   = m >> 4;
            int half  = (m >> 3) & 1;
            int regIdx = ((colk4 >> 1) << 1) + half;       // 0..3
            int lane0  = (m & 7) * 4 + (colk4 & 1) * 2;
            uint32_t off_h = ((((s * 2 + 0) * 4 + mtg) * 32) + lane0) * 16 + regIdx * 4;
            uint32_t off_l = off_h + 2048;                 // comp stride = 4*32*16
            __half2 h0 = __floats2half2_rn(x.x, x.y);
            __half2 h1 = __floats2half2_rn(x.z, x.w);
            float2 f0 = __half22float2(h0);
            float2 f1 = __half22float2(h1);
            __half2 l0 = __floats2half2_rn(x.x - f0.x, x.y - f0.y);
            __half2 l1 = __floats2half2_rn(x.z - f1.x, x.w - f1.y);
            *reinterpret_cast<uint32_t*>(smem + XF_OFF + off_h)      = *reinterpret_cast<uint32_t*>(&h0);
            *reinterpret_cast<uint32_t*>(smem + XF_OFF + off_h + 16) = *reinterpret_cast<uint32_t*>(&h1);
            *reinterpret_cast<uint32_t*>(smem + XF_OFF + off_l)      = *reinterpret_cast<uint32_t*>(&l0);
            *reinterpret_cast<uint32_t*>(smem + XF_OFF + off_l + 16) = *reinterpret_cast<uint32_t*>(&l1);
        }
    }
    // aux
    {
        float2* wb = reinterpret_cast<float2*>(smem + W2B1_OFF);
        wb[t] = make_float2(b1[t], W2[t]);
        if (t < Lq) {
            float dx = src_locs[(b * Lq + t) * 2 + 0] - tar_locs[b * 2 + 0];
            float dy = src_locs[(b * Lq + t) * 2 + 1] - tar_locs[b * 2 + 1];
            reinterpret_cast<float*>(smem + INVD_OFF)[t] = rsqrtf(dx * dx + dy * dy);
        }
    }
    CP_WAIT0();
    __syncthreads();

    // ---- mainloop: 16 K-steps, 2-term fp16 (Ah*B + Al*B) ----
    float acc[2][8][4];
    #pragma unroll
    for (int mt = 0; mt < 2; ++mt)
        #pragma unroll
        for (int nt = 0; nt < 8; ++nt)
            #pragma unroll
            for (int k = 0; k < 4; ++k) acc[mt][nt][k] = 0.f;

    #pragma unroll 1
    for (int s = 0; s < 16; ++s) {
        if (s < 15) {
            uint32_t dstb = sb + WB_OFF + ((s + 1) & 1) * 8192;
            const uint4* srcb = g_Wf + (s + 1) * 512;
            #pragma unroll
            for (int j = 0; j < 2; ++j) {
                int seg = t + j * 256;
                cp16(dstb + seg * 16, srcb + seg);
            }
            CP_COMMIT();
        }

        const char* stage = smem + WB_OFF + (s & 1) * 8192;
        const char* xf    = smem + XF_OFF + (s * 2) * 2048;

        uint4 Ah[2], Al[2];
        #pragma unroll
        for (int mt = 0; mt < 2; ++mt) {
            int mtg = warp_m * 2 + mt;
            Ah[mt] = *reinterpret_cast<const uint4*>(xf + (mtg * 32 + lane) * 16);
            Al[mt] = *reinterpret_cast<const uint4*>(xf + 2048 + (mtg * 32 + lane) * 16);
        }
        uint4 Bf[4];
        #pragma unroll
        for (int i = 0; i < 4; ++i)
            Bf[i] = *reinterpret_cast<const uint4*>(
                stage + ((warp_n * 4 + i) * 32 + lane) * 16);

        #pragma unroll
        for (int i = 0; i < 4; ++i) {
            mma16816(acc[0][i * 2 + 0], Ah[0], Bf[i].x, Bf[i].y);
            mma16816(acc[1][i * 2 + 0], Ah[1], Bf[i].x, Bf[i].y);
            mma16816(acc[0][i * 2 + 1], Ah[0], Bf[i].z, Bf[i].w);
            mma16816(acc[1][i * 2 + 1], Ah[1], Bf[i].z, Bf[i].w);
            mma16816(acc[0][i * 2 + 0], Al[0], Bf[i].x, Bf[i].y);
            mma16816(acc[1][i * 2 + 0], Al[1], Bf[i].x, Bf[i].y);
            mma16816(acc[0][i * 2 + 1], Al[0], Bf[i].z, Bf[i].w);
            mma16816(acc[1][i * 2 + 1], Al[1], Bf[i].z, Bf[i].w);
        }
        if (s < 15) {
            CP_WAIT0();
            __syncthreads();
        }
    }

    // ---- register epilogue: p = sum_col relu(D+b1)*W2, quad-reduce ----
    {
        const float2* wb = reinterpret_cast<const float2*>(smem + W2B1_OFF);
        float* pred = reinterpret_cast<float*>(smem + PRED_OFF);
        #pragma unroll
        for (int mt = 0; mt < 2; ++mt) {
            float p0 = 0.f, p1 = 0.f;
            #pragma unroll
            for (int nt = 0; nt < 8; ++nt) {
                int col0 = warp_n * 64 + nt * 8 + q * 2;
                float2 c0 = wb[col0];
                float2 c1 = wb[col0 + 1];
                const float* c = acc[mt][nt];
                p0 = fmaf(fmaxf(c[0] + c0.x, 0.f), c0.y, p0);
                p0 = fmaf(fmaxf(c[1] + c1.x, 0.f), c1.y, p0);
                p1 = fmaf(fmaxf(c[2] + c0.x, 0.f), c0.y, p1);
                p1 = fmaf(fmaxf(c[3] + c1.x, 0.f), c1.y, p1);
            }
            #pragma unroll
            for (int off = 1; off < 4; off <<= 1) {
                p0 += __shfl_xor_sync(0xffffffffu, p0, off);
                p1 += __shfl_xor_sync(0xffffffffu, p1, off);
            }
            if (q == 0) {
                int row = warp_m * 32 + mt * 16 + g;
                pred[warp_n * 64 + row]     = p0;
                pred[warp_n * 64 + row + 8] = p1;
            }
        }
    }
    __syncthreads();
    {
        const float* pred = reinterpret_cast<const float*>(smem + PRED_OFF);
        if (t < 64) {
            float ptot = pred[t] + pred[t + 64] + pred[t + 128] + pred[t + 192];
            float sscore = fmaxf(ptot + b2[0], 0.f) *
                           reinterpret_cast<const float*>(smem + INVD_OFF)[t];
            reinterpret_cast<float*>(smem + SC_OFF)[t] = sscore;
        }
    }
    __syncthreads();

    // ---- softmax over L=64 (warp 0) ----
    if (wid == 0) {
        const float* sc = reinterpret_cast<const float*>(smem + SC_OFF);
        float* wg = reinterpret_cast<float*>(smem + WGT_OFF);
        float s0 = sc[lane], s1 = sc[lane + 32];
        float m = fmaxf(s0, s1);
        #pragma unroll
        for (int off = 16; off > 0; off >>= 1)
            m = fmaxf(m, __shfl_xor_sync(0xffffffffu, m, off));
        float e0 = expf(s0 - m), e1 = expf(s1 - m);
        float ssum = e0 + e1;
        #pragma unroll
        for (int off = 16; off > 0; off >>= 1)
            ssum += __shfl_xor_sync(0xffffffffu, ssum, off);
        float inv = 1.f / ssum;
        wg[lane] = e0 * inv;
        wg[lane + 32] = e1 * inv;
    }
    __syncthreads();

    // ---- phase 5: out[bs,:] = sum_l wgt[l] * features[bs,l,:], float4-vectorized ----
    {
        const float* wg = reinterpret_cast<const float*>(smem + WGT_OFF);
        const float4* fx = reinterpret_cast<const float4*>(features + (size_t)bs * (Lq * Fq));
        float4* pred4 = reinterpret_cast<float4*>(smem + PRED_OFF);
        const int fb  = t & 63;          // float4 column block
        const int sub = t >> 6;          // row-group: l in [sub*16, +16)
        float4 o = make_float4(0.f, 0.f, 0.f, 0.f);
        #pragma unroll 4
        for (int i = 0; i < 16; ++i) {
            int l = sub * 16 + i;
            float w = wg[l];
            float4 x = fx[l * 64 + fb];
            o.x = fmaf(w, x.x, o.x);
            o.y = fmaf(w, x.y, o.y);
            o.z = fmaf(w, x.z, o.z);
            o.w = fmaf(w, x.w, o.w);
        }
        pred4[t] = o;
    }
    __syncthreads();
    if (t < 64) {
        const float4* pred4 = reinterpret_cast<const float4*>(smem + PRED_OFF);
        float4 a0 = pred4[t], a1 = pred4[t + 64], a2 = pred4[t + 128], a3 = pred4[t + 192];
        float4 o;
        o.x = a0.x + a1.x + a2.x + a3.x;
        o.y = a0.y + a1.y + a2.y + a3.y;
        o.z = a0.z + a1.z + a2.z + a3.z;
        o.w = a0.w + a1.w + a2.w + a3.w;
        reinterpret_cast<float4*>(out + (size_t)bs * Fq)[t] = o;
    }
}

extern "C" void kernel_launch(void* const* d_in, const int* in_sizes, int n_in,
                              void* d_out, int out_size)
{
    const float* features = (const float*)d_in[0];
    const float* src_locs = (const float*)d_in[1];
    const float* tar_locs = (const float*)d_in[2];
    const float* W1       = (const float*)d_in[3];
    const float* b1       = (const float*)d_in[4];
    const float* W2       = (const float*)d_in[5];
    const float* b2       = (const float*)d_in[6];
    float* out            = (float*)d_out;

    stage_w1_kernel<<<32, 256>>>(W1);

    cudaFuncSetAttribute(ida_mma_kernel,
                         cudaFuncAttributeMaxDynamicSharedMemorySize, SMEM_BYTES);
    ida_mma_kernel<<<Bq * Sq, 256, SMEM_BYTES>>>(
        features, src_locs, tar_locs, b1, W2, b2, out);
}

// round 11
// speedup vs baseline: 1.5466x; 1.5466x over previous
#include <cuda_runtime.h>
#include <cuda_fp16.h>
#include <cstdint>

#define Bq 32
#define Sq 48
#define Lq 64
#define Fq 256

// ---------------- staged W1 in mma.sync B-fragment layout (fp16, single comp) ----------------
// g_Wf[(s*16 + nbp)*32 + lane] : uint4 = two n8-fragments {b0,b1} for nblocks 2*nbp, 2*nbp+1
__device__ __align__(16) uint4 g_Wf[16 * 16 * 32];   // 128KB

__device__ __forceinline__ uint32_t pack_h(float lo, float hi) {
    __half2 h = __floats2half2_rn(lo, hi);
    return *reinterpret_cast<uint32_t*>(&h);
}

__global__ void stage_w1_kernel(const float* __restrict__ W1) {
    int idx = blockIdx.x * 256 + threadIdx.x;   // 8192 uint4s
    int lane = idx & 31;
    int nbp  = (idx >> 5) & 15;
    int s    = idx >> 9;
    int g = lane >> 2, q = lane & 3;
    int k0 = s * 16 + q * 2;
    uint4 r;
    uint32_t* rr = reinterpret_cast<uint32_t*>(&r);
    #pragma unroll
    for (int h = 0; h < 2; ++h) {
        int col = (nbp * 2 + h) * 8 + g;
        rr[h * 2 + 0] = pack_h(W1[(k0 + 0) * 256 + col], W1[(k0 + 1) * 256 + col]);
        rr[h * 2 + 1] = pack_h(W1[(k0 + 8) * 256 + col], W1[(k0 + 9) * 256 + col]);
    }
    g_Wf[idx] = r;
}

// ---------------- helpers ----------------
__device__ __forceinline__ uint32_t smem_u32(const void* p) {
    uint32_t a;
    asm("{ .reg .u64 t; cvta.to.shared.u64 t, %1; cvt.u32.u64 %0, t; }" : "=r"(a) : "l"(p));
    return a;
}
__device__ __forceinline__ void cp16(uint32_t dst, const void* src) {
    asm volatile("cp.async.ca.shared.global [%0], [%1], 16;" :: "r"(dst), "l"(src));
}
#define CP_COMMIT()   asm volatile("cp.async.commit_group;" ::: "memory")
#define CP_WAIT_ALL() asm volatile("cp.async.wait_group 0;" ::: "memory")

__device__ __forceinline__ void mma16816(float* c, const uint4& a, uint32_t b0, uint32_t b1) {
    asm volatile(
        "mma.sync.aligned.m16n8k16.row.col.f32.f16.f16.f32 "
        "{%0,%1,%2,%3},{%4,%5,%6,%7},{%8,%9},{%0,%1,%2,%3};"
        : "+f"(c[0]), "+f"(c[1]), "+f"(c[2]), "+f"(c[3])
        : "r"(a.x), "r"(a.y), "r"(a.z), "r"(a.w), "r"(b0), "r"(b1));
}

// ---------------- SMEM layout (bytes) ----------------
// Xf: A-fragment layout [s 16][comp 2][mtg 4][lane 32] uint4 = 64KB  (comp: Ah, Al)
static constexpr int XF_OFF   = 0;
static constexpr int WB_OFF   = 65536;    // 4-stage ring x 8KB = 32KB
static constexpr int PRED_OFF = 98304;    // float4[256] = 4KB
static constexpr int W2B1_OFF = 102400;   // float2[256] = 2KB
static constexpr int INVD_OFF = 104448;   // float[64]
static constexpr int SC_OFF   = 104704;   // float[64]
static constexpr int WGT_OFF  = 104960;   // float[64]
static constexpr int SMEM_BYTES = 105216;

__global__ __launch_bounds__(256, 2)
void ida_mma_kernel(const float* __restrict__ features,
                    const float* __restrict__ src_locs,
                    const float* __restrict__ tar_locs,
                    const float* __restrict__ b1,
                    const float* __restrict__ W2,
                    const float* __restrict__ b2,
                    float* __restrict__ out)
{
    extern __shared__ char smem[];
    const uint32_t sb = smem_u32(smem);
    const int t      = threadIdx.x;
    const int lane   = t & 31;
    const int wid    = t >> 5;
    const int warp_m = wid & 1;        // rows [warp_m*32, +32)
    const int warp_n = wid >> 1;       // cols [warp_n*64, +64)
    const int g      = lane >> 2;
    const int q      = lane & 3;
    const int bs     = blockIdx.x;
    const int b      = bs / Sq;

    // ---- prologue: cp.async W stages 0,1 (one commit group each) ----
    #pragma unroll
    for (int p = 0; p < 2; ++p) {
        #pragma unroll
        for (int j = 0; j < 2; ++j) {
            int seg = t + j * 256;               // 512 uint4s per stage
            cp16(sb + WB_OFF + p * 8192 + seg * 16, g_Wf + p * 512 + seg);
        }
        CP_COMMIT();
    }

    // ---- convert X (64x256 f32) into fp16 A-fragment layout, hi + lo ----
    {
        const float4* gx = reinterpret_cast<const float4*>(features + (size_t)bs * (Lq * Fq));
        #pragma unroll
        for (int r = 0; r < 16; ++r) {
            int idx = t + r * 256;          // float4 index = m*64 + qq
            int m = idx >> 6, qq = idx & 63;
            float4 x = gx[idx];
            int s     = qq >> 2;
            int colk4 = qq & 3;
            int mtg   = m >> 4;
            int half  = (m >> 3) & 1;
            int regIdx = ((colk4 >> 1) << 1) + half;       // 0..3
            int lane0  = (m & 7) * 4 + (colk4 & 1) * 2;
            uint32_t off_h = ((((s * 2 + 0) * 4 + mtg) * 32) + lane0) * 16 + regIdx * 4;
            uint32_t off_l = off_h + 2048;                 // comp stride = 4*32*16
            __half2 h0 = __floats2half2_rn(x.x, x.y);
            __half2 h1 = __floats2half2_rn(x.z, x.w);
            float2 f0 = __half22float2(h0);
            float2 f1 = __half22float2(h1);
            __half2 l0 = __floats2half2_rn(x.x - f0.x, x.y - f0.y);
            __half2 l1 = __floats2half2_rn(x.z - f1.x, x.w - f1.y);
            *reinterpret_cast<uint32_t*>(smem + XF_OFF + off_h)      = *reinterpret_cast<uint32_t*>(&h0);
            *reinterpret_cast<uint32_t*>(smem + XF_OFF + off_h + 16) = *reinterpret_cast<uint32_t*>(&h1);
            *reinterpret_cast<uint32_t*>(smem + XF_OFF + off_l)      = *reinterpret_cast<uint32_t*>(&l0);
            *reinterpret_cast<uint32_t*>(smem + XF_OFF + off_l + 16) = *reinterpret_cast<uint32_t*>(&l1);
        }
    }
    // aux
    {
        float2* wb = reinterpret_cast<float2*>(smem + W2B1_OFF);
        wb[t] = make_float2(b1[t], W2[t]);
        if (t < Lq) {
            float dx = src_locs[(b * Lq + t) * 2 + 0] - tar_locs[b * 2 + 0];
            float dy = src_locs[(b * Lq + t) * 2 + 1] - tar_locs[b * 2 + 1];
            reinterpret_cast<float*>(smem + INVD_OFF)[t] = rsqrtf(dx * dx + dy * dy);
        }
    }

    // ---- mainloop: 8 iterations x 2 K-steps, 4-stage ring, prefetch distance 2 ----
    float acc[2][8][4];
    #pragma unroll
    for (int mt = 0; mt < 2; ++mt)
        #pragma unroll
        for (int nt = 0; nt < 8; ++nt)
            #pragma unroll
            for (int k = 0; k < 4; ++k) acc[mt][nt][k] = 0.f;

    #pragma unroll 1
    for (int it = 0; it < 8; ++it) {
        const int s0 = it * 2;
        CP_WAIT_ALL();            // stages s0, s0+1 resident
        __syncthreads();          // all warps done with ring slots being overwritten below

        if (it < 7) {             // prefetch stages s0+2, s0+3 into slots (s0+2)&3, (s0+3)&3
            #pragma unroll
            for (int p = 0; p < 2; ++p) {
                int stg = s0 + 2 + p;
                uint32_t dstb = sb + WB_OFF + (stg & 3) * 8192;
                const uint4* srcb = g_Wf + stg * 512;
                #pragma unroll
                for (int j = 0; j < 2; ++j) {
                    int seg = t + j * 256;
                    cp16(dstb + seg * 16, srcb + seg);
                }
                CP_COMMIT();
            }
        }

        const char* st0 = smem + WB_OFF + ((s0 + 0) & 3) * 8192;
        const char* st1 = smem + WB_OFF + ((s0 + 1) & 3) * 8192;
        const char* xf0 = smem + XF_OFF + (s0 * 2) * 2048;
        const char* xf1 = xf0 + 4096;

        uint4 A0h[2], A0l[2], A1h[2], A1l[2];
        #pragma unroll
        for (int mt = 0; mt < 2; ++mt) {
            int mtg = warp_m * 2 + mt;
            A0h[mt] = *reinterpret_cast<const uint4*>(xf0 + (mtg * 32 + lane) * 16);
            A0l[mt] = *reinterpret_cast<const uint4*>(xf0 + 2048 + (mtg * 32 + lane) * 16);
            A1h[mt] = *reinterpret_cast<const uint4*>(xf1 + (mtg * 32 + lane) * 16);
            A1l[mt] = *reinterpret_cast<const uint4*>(xf1 + 2048 + (mtg * 32 + lane) * 16);
        }

        #pragma unroll
        for (int i = 0; i < 4; ++i) {
            uint4 B0 = *reinterpret_cast<const uint4*>(st0 + ((warp_n * 4 + i) * 32 + lane) * 16);
            mma16816(acc[0][i * 2 + 0], A0h[0], B0.x, B0.y);
            mma16816(acc[1][i * 2 + 0], A0h[1], B0.x, B0.y);
            mma16816(acc[0][i * 2 + 1], A0h[0], B0.z, B0.w);
            mma16816(acc[1][i * 2 + 1], A0h[1], B0.z, B0.w);
            mma16816(acc[0][i * 2 + 0], A0l[0], B0.x, B0.y);
            mma16816(acc[1][i * 2 + 0], A0l[1], B0.x, B0.y);
            mma16816(acc[0][i * 2 + 1], A0l[0], B0.z, B0.w);
            mma16816(acc[1][i * 2 + 1], A0l[1], B0.z, B0.w);
        }
        #pragma unroll
        for (int i = 0; i < 4; ++i) {
            uint4 B1 = *reinterpret_cast<const uint4*>(st1 + ((warp_n * 4 + i) * 32 + lane) * 16);
            mma16816(acc[0][i * 2 + 0], A1h[0], B1.x, B1.y);
            mma16816(acc[1][i * 2 + 0], A1h[1], B1.x, B1.y);
            mma16816(acc[0][i * 2 + 1], A1h[0], B1.z, B1.w);
            mma16816(acc[1][i * 2 + 1], A1h[1], B1.z, B1.w);
            mma16816(acc[0][i * 2 + 0], A1l[0], B1.x, B1.y);
            mma16816(acc[1][i * 2 + 0], A1l[1], B1.x, B1.y);
            mma16816(acc[0][i * 2 + 1], A1l[0], B1.z, B1.w);
            mma16816(acc[1][i * 2 + 1], A1l[1], B1.z, B1.w);
        }
    }

    // ---- register epilogue: p = sum_col relu(D+b1)*W2, quad-reduce ----
    {
        const float2* wb = reinterpret_cast<const float2*>(smem + W2B1_OFF);
        float* pred = reinterpret_cast<float*>(smem + PRED_OFF);
        #pragma unroll
        for (int mt = 0; mt < 2; ++mt) {
            float p0 = 0.f, p1 = 0.f;
            #pragma unroll
            for (int nt = 0; nt < 8; ++nt) {
                int col0 = warp_n * 64 + nt * 8 + q * 2;
                float2 c0 = wb[col0];
                float2 c1 = wb[col0 + 1];
                const float* c = acc[mt][nt];
                p0 = fmaf(fmaxf(c[0] + c0.x, 0.f), c0.y, p0);
                p0 = fmaf(fmaxf(c[1] + c1.x, 0.f), c1.y, p0);
                p1 = fmaf(fmaxf(c[2] + c0.x, 0.f), c0.y, p1);
                p1 = fmaf(fmaxf(c[3] + c1.x, 0.f), c1.y, p1);
            }
            #pragma unroll
            for (int off = 1; off < 4; off <<= 1) {
                p0 += __shfl_xor_sync(0xffffffffu, p0, off);
                p1 += __shfl_xor_sync(0xffffffffu, p1, off);
            }
            if (q == 0) {
                int row = warp_m * 32 + mt * 16 + g;
                pred[warp_n * 64 + row]     = p0;
                pred[warp_n * 64 + row + 8] = p1;
            }
        }
    }
    __syncthreads();
    {
        const float* pred = reinterpret_cast<const float*>(smem + PRED_OFF);
        if (t < 64) {
            float ptot = pred[t] + pred[t + 64] + pred[t + 128] + pred[t + 192];
            float sscore = fmaxf(ptot + b2[0], 0.f) *
                           reinterpret_cast<const float*>(smem + INVD_OFF)[t];
            reinterpret_cast<float*>(smem + SC_OFF)[t] = sscore;
        }
    }
    __syncthreads();

    // ---- softmax over L=64 (warp 0) ----
    if (wid == 0) {
        const float* sc = reinterpret_cast<const float*>(smem + SC_OFF);
        float* wg = reinterpret_cast<float*>(smem + WGT_OFF);
        float s0 = sc[lane], s1 = sc[lane + 32];
        float m = fmaxf(s0, s1);
        #pragma unroll
        for (int off = 16; off > 0; off >>= 1)
            m = fmaxf(m, __shfl_xor_sync(0xffffffffu, m, off));
        float e0 = expf(s0 - m), e1 = expf(s1 - m);
        float ssum = e0 + e1;
        #pragma unroll
        for (int off = 16; off > 0; off >>= 1)
            ssum += __shfl_xor_sync(0xffffffffu, ssum, off);
        float inv = 1.f / ssum;
        wg[lane] = e0 * inv;
        wg[lane + 32] = e1 * inv;
    }
    __syncthreads();

    // ---- phase 5: out[bs,:] = sum_l wgt[l] * features[bs,l,:], float4-vectorized ----
    {
        const float* wg = reinterpret_cast<const float*>(smem + WGT_OFF);
        const float4* fx = reinterpret_cast<const float4*>(features + (size_t)bs * (Lq * Fq));
        float4* pred4 = reinterpret_cast<float4*>(smem + PRED_OFF);
        const int fb  = t & 63;          // float4 column block
        const int sub = t >> 6;          // row-group: l in [sub*16, +16)
        float4 o = make_float4(0.f, 0.f, 0.f, 0.f);
        #pragma unroll 4
        for (int i = 0; i < 16; ++i) {
            int l = sub * 16 + i;
            float w = wg[l];
            float4 x = fx[l * 64 + fb];
            o.x = fmaf(w, x.x, o.x);
            o.y = fmaf(w, x.y, o.y);
            o.z = fmaf(w, x.z, o.z);
            o.w = fmaf(w, x.w, o.w);
        }
        pred4[t] = o;
    }
    __syncthreads();
    if (t < 64) {
        const float4* pred4 = reinterpret_cast<const float4*>(smem + PRED_OFF);
        float4 a0 = pred4[t], a1 = pred4[t + 64], a2 = pred4[t + 128], a3 = pred4[t + 192];
        float4 o;
        o.x = a0.x + a1.x + a2.x + a3.x;
        o.y = a0.y + a1.y + a2.y + a3.y;
        o.z = a0.z + a1.z + a2.z + a3.z;
        o.w = a0.w + a1.w + a2.w + a3.w;
        reinterpret_cast<float4*>(out + (size_t)bs * Fq)[t] = o;
    }
}

extern "C" void kernel_launch(void* const* d_in, const int* in_sizes, int n_in,
                              void* d_out, int out_size)
{
    const float* features = (const float*)d_in[0];
    const float* src_locs = (const float*)d_in[1];
    const float* tar_locs = (const float*)d_in[2];
    const float* W1       = (const float*)d_in[3];
    const float* b1       = (const float*)d_in[4];
    const float* W2       = (const float*)d_in[5];
    const float* b2       = (const float*)d_in[6];
    float* out            = (float*)d_out;

    stage_w1_kernel<<<32, 256>>>(W1);

    cudaFuncSetAttribute(ida_mma_kernel,
                         cudaFuncAttributeMaxDynamicSharedMemorySize, SMEM_BYTES);
    ida_mma_kernel<<<Bq * Sq, 256, SMEM_BYTES>>>(
        features, src_locs, tar_locs, b1, W2, b2, out);
}

// round 12
// speedup vs baseline: 1.6105x; 1.0413x over previous
#include <cuda_runtime.h>
#include <cuda_fp16.h>
#include <cstdint>

#define Bq 32
#define Sq 48
#define Lq 64
#define Fq 256
#define NTILES (Bq * Sq)
#define GRID 152

// ---------------- staged W1 in mma.sync B-fragment layout (fp16) ----------------
// g_Wf[(s*16 + nbp)*32 + lane] : uint4 = two n8-fragments {b0,b1} for nblocks 2*nbp, 2*nbp+1
__device__ __align__(16) uint4 g_Wf[16 * 16 * 32];   // 128KB

__device__ __forceinline__ uint32_t pack_h(float lo, float hi) {
    __half2 h = __floats2half2_rn(lo, hi);
    return *reinterpret_cast<uint32_t*>(&h);
}

__global__ void stage_w1_kernel(const float* __restrict__ W1) {
    int idx = blockIdx.x * 256 + threadIdx.x;   // 8192 uint4s
    int lane = idx & 31;
    int nbp  = (idx >> 5) & 15;
    int s    = idx >> 9;
    int g = lane >> 2, q = lane & 3;
    int k0 = s * 16 + q * 2;
    uint4 r;
    uint32_t* rr = reinterpret_cast<uint32_t*>(&r);
    #pragma unroll
    for (int h = 0; h < 2; ++h) {
        int col = (nbp * 2 + h) * 8 + g;
        rr[h * 2 + 0] = pack_h(W1[(k0 + 0) * 256 + col], W1[(k0 + 1) * 256 + col]);
        rr[h * 2 + 1] = pack_h(W1[(k0 + 8) * 256 + col], W1[(k0 + 9) * 256 + col]);
    }
    g_Wf[idx] = r;
}

// ---------------- helpers ----------------
__device__ __forceinline__ uint32_t smem_u32(const void* p) {
    uint32_t a;
    asm("{ .reg .u64 t; cvta.to.shared.u64 t, %1; cvt.u32.u64 %0, t; }" : "=r"(a) : "l"(p));
    return a;
}
__device__ __forceinline__ void cp16(uint32_t dst, const void* src) {
    asm volatile("cp.async.ca.shared.global [%0], [%1], 16;" :: "r"(dst), "l"(src));
}
#define CP_COMMIT()   asm volatile("cp.async.commit_group;" ::: "memory")
#define CP_WAIT_ALL() asm volatile("cp.async.wait_group 0;" ::: "memory")

__device__ __forceinline__ void mma16816(float* c, const uint4& a, uint32_t b0, uint32_t b1) {
    asm volatile(
        "mma.sync.aligned.m16n8k16.row.col.f32.f16.f16.f32 "
        "{%0,%1,%2,%3},{%4,%5,%6,%7},{%8,%9},{%0,%1,%2,%3};"
        : "+f"(c[0]), "+f"(c[1]), "+f"(c[2]), "+f"(c[3])
        : "r"(a.x), "r"(a.y), "r"(a.z), "r"(a.w), "r"(b0), "r"(b1));
}

// ---------------- SMEM layout (bytes) ----------------
static constexpr int WF_OFF   = 0;         // resident W1 fragments: 16 stages x 8KB = 128KB
static constexpr int XF_OFF   = 131072;    // X A-fragments [s16][comp2][mtg4][lane32] uint4 = 64KB
static constexpr int PRED_OFF = 196608;    // float4[512] = 8KB (also float pred[512])
static constexpr int W2B1_OFF = 204800;    // float2[256] = 2KB
static constexpr int INVD_OFF = 206848;    // float[64]
static constexpr int SC_OFF   = 207104;    // float[64]
static constexpr int WGT_OFF  = 207360;    // float[64]
static constexpr int SMEM_BYTES = 207616;

__global__ __launch_bounds__(512, 1)
void ida_mma_kernel(const float* __restrict__ features,
                    const float* __restrict__ src_locs,
                    const float* __restrict__ tar_locs,
                    const float* __restrict__ b1,
                    const float* __restrict__ W2,
                    const float* __restrict__ b2,
                    float* __restrict__ out)
{
    extern __shared__ char smem[];
    const uint32_t sb = smem_u32(smem);
    const int t      = threadIdx.x;
    const int lane   = t & 31;
    const int wid    = t >> 5;
    const int warp_m = wid & 1;        // rows [warp_m*32, +32)
    const int warp_n = wid >> 1;       // cols [warp_n*32, +32)
    const int g      = lane >> 2;
    const int q      = lane & 3;

    // ---- one-time: cp.async entire W1 fragment image (128KB) ----
    {
        #pragma unroll
        for (int j = 0; j < 16; ++j) {
            int seg = t + j * 512;               // 8192 uint4s
            cp16(sb + WF_OFF + seg * 16, g_Wf + seg);
        }
        CP_COMMIT();
    }
    if (t < 256) {
        float2* wb = reinterpret_cast<float2*>(smem + W2B1_OFF);
        wb[t] = make_float2(b1[t], W2[t]);
    }
    const float b2v = b2[0];

    // ---- tile loop: bs strided across the grid ----
    #pragma unroll 1
    for (int bs = blockIdx.x; bs < NTILES; bs += GRID) {
        const int b = bs / Sq;

        __syncthreads();   // prior tile fully done with Xf/invd/wgt consumers

        // ---- convert X (64x256 f32) into fp16 A-fragment layout, hi + lo ----
        {
            const float4* gx = reinterpret_cast<const float4*>(features + (size_t)bs * (Lq * Fq));
            #pragma unroll
            for (int r = 0; r < 8; ++r) {
                int idx = t + r * 512;          // float4 index = m*64 + qq
                int m = idx >> 6, qq = idx & 63;
                float4 x = gx[idx];
                int s     = qq >> 2;
                int colk4 = qq & 3;
                int mtg   = m >> 4;
                int half  = (m >> 3) & 1;
                int regIdx = ((colk4 >> 1) << 1) + half;       // 0..3
                int lane0  = (m & 7) * 4 + (colk4 & 1) * 2;
                uint32_t off_h = ((((s * 2 + 0) * 4 + mtg) * 32) + lane0) * 16 + regIdx * 4;
                uint32_t off_l = off_h + 2048;                 // comp stride = 4*32*16
                __half2 h0 = __floats2half2_rn(x.x, x.y);
                __half2 h1 = __floats2half2_rn(x.z, x.w);
                float2 f0 = __half22float2(h0);
                float2 f1 = __half22float2(h1);
                __half2 l0 = __floats2half2_rn(x.x - f0.x, x.y - f0.y);
                __half2 l1 = __floats2half2_rn(x.z - f1.x, x.w - f1.y);
                *reinterpret_cast<uint32_t*>(smem + XF_OFF + off_h)      = *reinterpret_cast<uint32_t*>(&h0);
                *reinterpret_cast<uint32_t*>(smem + XF_OFF + off_h + 16) = *reinterpret_cast<uint32_t*>(&h1);
                *reinterpret_cast<uint32_t*>(smem + XF_OFF + off_l)      = *reinterpret_cast<uint32_t*>(&l0);
                *reinterpret_cast<uint32_t*>(smem + XF_OFF + off_l + 16) = *reinterpret_cast<uint32_t*>(&l1);
            }
        }
        if (t < Lq) {
            float dx = src_locs[(b * Lq + t) * 2 + 0] - tar_locs[b * 2 + 0];
            float dy = src_locs[(b * Lq + t) * 2 + 1] - tar_locs[b * 2 + 1];
            reinterpret_cast<float*>(smem + INVD_OFF)[t] = rsqrtf(dx * dx + dy * dy);
        }
        CP_WAIT_ALL();     // W1 resident (no-op after first tile)
        __syncthreads();

        // ---- mainloop: 16 K-steps, everything SMEM-resident, no barriers ----
        float acc[2][4][4];
        #pragma unroll
        for (int mt = 0; mt < 2; ++mt)
            #pragma unroll
            for (int nt = 0; nt < 4; ++nt)
                #pragma unroll
                for (int k = 0; k < 4; ++k) acc[mt][nt][k] = 0.f;

        #pragma unroll
        for (int s = 0; s < 16; ++s) {
            const char* wfs = smem + WF_OFF + s * 8192;
            const char* xfs = smem + XF_OFF + s * 4096;

            uint4 Ah[2], Al[2];
            #pragma unroll
            for (int mt = 0; mt < 2; ++mt) {
                int mtg = warp_m * 2 + mt;
                Ah[mt] = *reinterpret_cast<const uint4*>(xfs + (mtg * 32 + lane) * 16);
                Al[mt] = *reinterpret_cast<const uint4*>(xfs + 2048 + (mtg * 32 + lane) * 16);
            }
            #pragma unroll
            for (int j = 0; j < 2; ++j) {
                uint4 B = *reinterpret_cast<const uint4*>(
                    wfs + ((warp_n * 2 + j) * 32 + lane) * 16);
                mma16816(acc[0][j * 2 + 0], Ah[0], B.x, B.y);
                mma16816(acc[1][j * 2 + 0], Ah[1], B.x, B.y);
                mma16816(acc[0][j * 2 + 1], Ah[0], B.z, B.w);
                mma16816(acc[1][j * 2 + 1], Ah[1], B.z, B.w);
                mma16816(acc[0][j * 2 + 0], Al[0], B.x, B.y);
                mma16816(acc[1][j * 2 + 0], Al[1], B.x, B.y);
                mma16816(acc[0][j * 2 + 1], Al[0], B.z, B.w);
                mma16816(acc[1][j * 2 + 1], Al[1], B.z, B.w);
            }
        }

        // ---- register epilogue: p = sum_col relu(D+b1)*W2, quad-reduce ----
        {
            const float2* wb = reinterpret_cast<const float2*>(smem + W2B1_OFF);
            float* pred = reinterpret_cast<float*>(smem + PRED_OFF);
            #pragma unroll
            for (int mt = 0; mt < 2; ++mt) {
                float p0 = 0.f, p1 = 0.f;
                #pragma unroll
                for (int nt = 0; nt < 4; ++nt) {
                    int col0 = warp_n * 32 + nt * 8 + q * 2;
                    float2 c0 = wb[col0];
                    float2 c1 = wb[col0 + 1];
                    const float* c = acc[mt][nt];
                    p0 = fmaf(fmaxf(c[0] + c0.x, 0.f), c0.y, p0);
                    p0 = fmaf(fmaxf(c[1] + c1.x, 0.f), c1.y, p0);
                    p1 = fmaf(fmaxf(c[2] + c0.x, 0.f), c0.y, p1);
                    p1 = fmaf(fmaxf(c[3] + c1.x, 0.f), c1.y, p1);
                }
                #pragma unroll
                for (int off = 1; off < 4; off <<= 1) {
                    p0 += __shfl_xor_sync(0xffffffffu, p0, off);
                    p1 += __shfl_xor_sync(0xffffffffu, p1, off);
                }
                if (q == 0) {
                    int row = warp_m * 32 + mt * 16 + g;
                    pred[warp_n * 64 + row]     = p0;
                    pred[warp_n * 64 + row + 8] = p1;
                }
            }
        }
        __syncthreads();
        if (t < 64) {
            const float* pred = reinterpret_cast<const float*>(smem + PRED_OFF);
            float ptot = 0.f;
            #pragma unroll
            for (int k = 0; k < 8; ++k) ptot += pred[t + k * 64];
            float sscore = fmaxf(ptot + b2v, 0.f) *
                           reinterpret_cast<const float*>(smem + INVD_OFF)[t];
            reinterpret_cast<float*>(smem + SC_OFF)[t] = sscore;
        }
        __syncthreads();

        // ---- softmax over L=64 (warp 0) ----
        if (wid == 0) {
            const float* sc = reinterpret_cast<const float*>(smem + SC_OFF);
            float* wg = reinterpret_cast<float*>(smem + WGT_OFF);
            float s0 = sc[lane], s1 = sc[lane + 32];
            float m = fmaxf(s0, s1);
            #pragma unroll
            for (int off = 16; off > 0; off >>= 1)
                m = fmaxf(m, __shfl_xor_sync(0xffffffffu, m, off));
            float e0 = expf(s0 - m), e1 = expf(s1 - m);
            float ssum = e0 + e1;
            #pragma unroll
            for (int off = 16; off > 0; off >>= 1)
                ssum += __shfl_xor_sync(0xffffffffu, ssum, off);
            float inv = 1.f / ssum;
            wg[lane] = e0 * inv;
            wg[lane + 32] = e1 * inv;
        }
        __syncthreads();

        // ---- phase 5: out[bs,:] = sum_l wgt[l] * features[bs,l,:] (L2-hot) ----
        {
            const float* wg = reinterpret_cast<const float*>(smem + WGT_OFF);
            const float4* fx = reinterpret_cast<const float4*>(features + (size_t)bs * (Lq * Fq));
            float4* pred4 = reinterpret_cast<float4*>(smem + PRED_OFF);
            const int fb  = t & 63;          // float4 column block
            const int sub = t >> 6;          // row-group: l in [sub*8, +8)
            float4 o = make_float4(0.f, 0.f, 0.f, 0.f);
            #pragma unroll
            for (int i = 0; i < 8; ++i) {
                int l = sub * 8 + i;
                float w = wg[l];
                float4 x = fx[l * 64 + fb];
                o.x = fmaf(w, x.x, o.x);
                o.y = fmaf(w, x.y, o.y);
                o.z = fmaf(w, x.z, o.z);
                o.w = fmaf(w, x.w, o.w);
            }
            pred4[t] = o;
        }
        __syncthreads();
        if (t < 64) {
            const float4* pred4 = reinterpret_cast<const float4*>(smem + PRED_OFF);
            float4 o = make_float4(0.f, 0.f, 0.f, 0.f);
            #pragma unroll
            for (int k = 0; k < 8; ++k) {
                float4 a = pred4[t + k * 64];
                o.x += a.x; o.y += a.y; o.z += a.z; o.w += a.w;
            }
            reinterpret_cast<float4*>(out + (size_t)bs * Fq)[t] = o;
        }
    }
}

extern "C" void kernel_launch(void* const* d_in, const int* in_sizes, int n_in,
                              void* d_out, int out_size)
{
    const float* features = (const float*)d_in[0];
    const float* src_locs = (const float*)d_in[1];
    const float* tar_locs = (const float*)d_in[2];
    const float* W1       = (const float*)d_in[3];
    const float* b1       = (const float*)d_in[4];
    const float* W2       = (const float*)d_in[5];
    const float* b2       = (const float*)d_in[6];
    float* out            = (float*)d_out;

    stage_w1_kernel<<<32, 256>>>(W1);

    cudaFuncSetAttribute(ida_mma_kernel,
                         cudaFuncAttributeMaxDynamicSharedMemorySize, SMEM_BYTES);
    ida_mma_kernel<<<GRID, 512, SMEM_BYTES>>>(
        features, src_locs, tar_locs, b1, W2, b2, out);
}